// round 17
// baseline (speedup 1.0000x reference)
#include <cuda_runtime.h>
#include <cuda_fp16.h>
#include <cstdint>

// Problem constants
#define SIG_HW 256
#define CIN    64
#define COUT   64
#define KS     31
#define PADK   15
#define NBATCH 8
#define NF     257           // rfft-512 bins

// GEMM smem geometry (uint32 units)
#define SB_STRIDE 296        // u32 per pair-row; 296%32==8 -> conflict-free
#define SB_ROWS   96         // 32 SrP + 32 SiP + 32 SsP(=Sr+Si)
#define WS_STRIDE 100        // u32 per o-row: ArP(32)|AiP(32)|AdP(32)|pad(4)
#define WS_ROWS   32         // o-half per block
#define WS_ELEMS  (WS_ROWS * WS_STRIDE)          // 3200 u32 per slot
#define WG_ROW    96         // u32 per o-row in global (no pad)
#define GX_WA     (SB_ROWS * SB_STRIDE)          // 28416
#define GX_TOTAL  (GX_WA + 2 * WS_ELEMS)         // 34816 u32 = 139264 B

// -------- device scratch --------
__device__ __half g_Sr[NBATCH * NF * CIN * 256];   // [b][f][c][y]
__device__ __half g_Si[NBATCH * NF * CIN * 256];
__device__ unsigned g_wA[NF * KS * COUT * WG_ROW]; // [f][ky][o][ArP|AiP|AdP]
__device__ float g_Or[NF * NBATCH * COUT * 256];   // [f][b][o][y]
__device__ float g_Oi[NF * NBATCH * COUT * 256];
__device__ float g_t256r[256], g_t256i[256];       // e^{-2pi i k/256}
__device__ float g_t512r[NF],  g_t512i[NF];        // e^{-2pi i k/512}

// base-4 digit reversal of 8-bit index
__device__ __forceinline__ int rev4(int n) {
    return ((n & 3) << 6) | ((n & 12) << 2) | ((n >> 2) & 12) | ((n >> 6) & 3);
}

__global__ void tw_init() {
    int k = threadIdx.x;
    if (k < 256) {
        float s, c;
        sincospif((float)k / 128.0f, &s, &c);
        g_t256r[k] = c; g_t256i[k] = -s;
    }
    if (k < NF) {
        float s, c;
        sincospif((float)k / 256.0f, &s, &c);
        g_t512r[k] = c; g_t512i[k] = -s;
    }
}

// ---------------------------------------------------------------------------
// In-smem 256-pt complex FFT, one warp, DIT radix-4, digit-reversed input.
// ---------------------------------------------------------------------------
__device__ __forceinline__ void fft256_r4(float* fr, float* fi,
                                          const float* twr, const float* twi,
                                          int lane) {
#pragma unroll
    for (int s = 0; s < 4; s++) {
        const int qsh     = 2 * s;
        const int quarter = 1 << qsh;
        const int step    = 64 >> qsh;
#pragma unroll
        for (int mm = 0; mm < 2; mm++) {
            const int m  = mm * 32 + lane;
            const int j  = m & (quarter - 1);
            const int i0 = ((m >> qsh) << (qsh + 2)) + j;
            const int i1 = i0 + quarter;
            const int i2 = i1 + quarter;
            const int i3 = i2 + quarter;
            const int tj = j * step;
            const float w1r = twr[tj],      w1i = twi[tj];
            const float w2r = twr[2 * tj],  w2i = twi[2 * tj];
            const float w3r = twr[3 * tj],  w3i = twi[3 * tj];
            const float x0r = fr[i0], x0i = fi[i0];
            const float x1r = fr[i1], x1i = fi[i1];
            const float x2r = fr[i2], x2i = fi[i2];
            const float x3r = fr[i3], x3i = fi[i3];
            const float b1r = w1r * x1r - w1i * x1i, b1i = w1r * x1i + w1i * x1r;
            const float b2r = w2r * x2r - w2i * x2i, b2i = w2r * x2i + w2i * x2r;
            const float b3r = w3r * x3r - w3i * x3i, b3i = w3r * x3i + w3i * x3r;
            const float p0r = x0r + b2r, p0i = x0i + b2i;
            const float m0r = x0r - b2r, m0i = x0i - b2i;
            const float p1r = b1r + b3r, p1i = b1i + b3i;
            const float m1r = b1r - b3r, m1i = b1i - b3i;
            fr[i0] = p0r + p1r;  fi[i0] = p0i + p1i;
            fr[i2] = p0r - p1r;  fi[i2] = p0i - p1i;
            fr[i1] = m0r + m1i;  fi[i1] = m0i - m1r;
            fr[i3] = m0r - m1i;  fi[i3] = m0i + m1r;
        }
        __syncwarp();
    }
}

// smem layout for FFT kernels (floats)
#define FX_T256R 0
#define FX_T256I 256
#define FX_T512R 512
#define FX_T512I (512 + 257)
#define FX_ROW   1026
#define FX_TSR   (FX_ROW + 8 * 512)
#define FX_TSI   (FX_TSR + 32 * NF)
#define FX_TOTAL (FX_TSI + 32 * NF)          // 21570 floats = 86280 B

__device__ __forceinline__ void load_tw(float* sm, int tid) {
    for (int i = tid; i < 256; i += 256) { sm[FX_T256R + i] = g_t256r[i]; sm[FX_T256I + i] = g_t256i[i]; }
    for (int i = tid; i < NF;  i += 256) { sm[FX_T512R + i] = g_t512r[i]; sm[FX_T512I + i] = g_t512i[i]; }
}

// rfft-512 of a real row (first L samples, rest zero) -> ts[yloc][0..256]
__device__ __forceinline__ void rfft_row(float* sm, const float* src, int L,
                                         int yloc, int lane, int warp) {
    float* fr = sm + FX_ROW + warp * 512;
    float* fi = fr + 256;
    for (int n = lane; n < 256; n += 32) {
        float xr = (2 * n < L)     ? src[2 * n]     : 0.f;
        float xi = (2 * n + 1 < L) ? src[2 * n + 1] : 0.f;
        int r = rev4(n);
        fr[r] = xr; fi[r] = xi;
    }
    __syncwarp();
    fft256_r4(fr, fi, sm + FX_T256R, sm + FX_T256I, lane);
    float* tsr = sm + FX_TSR + yloc * NF;
    float* tsi = sm + FX_TSI + yloc * NF;
    for (int k = lane; k <= 256; k += 32) {
        const int k1 = k & 255, k2 = (256 - k) & 255;
        const float zr1 = fr[k1], zi1 = fi[k1];
        const float zr2 = fr[k2], zi2 = fi[k2];
        const float Fer = 0.5f * (zr1 + zr2);
        const float Fei = 0.5f * (zi1 - zi2);
        const float Dr  = zr1 - zr2;
        const float Di  = zi1 + zi2;
        const float For = 0.5f * Di;
        const float Foi = -0.5f * Dr;
        const float wr = sm[FX_T512R + k], wi = sm[FX_T512I + k];
        tsr[k] = Fer + wr * For - wi * Foi;
        tsi[k] = Fei + wr * Foi + wi * For;
    }
    __syncwarp();
}

extern __shared__ float fx_sm[];

// ---------------------------------------------------------------------------
// Merged forward transform.
// Blocks [0,4096): signal rfft. CTA = (b, c, ytile of 32) -> g_Sr/g_Si (fp16).
// Blocks [4096,6080): weight direct DFT. CTA = (ky, o):
//   W[f] = sum_kx w·e^{-2pi i f kx/512}; stores Wr, Wi, Wd=Wr-Wi (fp16).
// ---------------------------------------------------------------------------
__global__ void __launch_bounds__(256) fwd_fft(const float* __restrict__ sig,
                                               const float* __restrict__ w) {
    const int tid = threadIdx.x, lane = tid & 31, warp = tid >> 5;

    if (blockIdx.x < 4096) {
        load_tw(fx_sm, tid);
        __syncthreads();
        const int ct = blockIdx.x;
        const int ytile = ct & 7, c = (ct >> 3) & 63, b = ct >> 9;
        for (int batch = 0; batch < 4; batch++) {
            const int yloc = batch * 8 + warp;
            const int y = ytile * 32 + yloc;
            const float* src = sig + (((b * 64 + c) * 256 + y) << 8);
            rfft_row(fx_sm, src, 256, yloc, lane, warp);
        }
        __syncthreads();
        for (int idx = tid; idx < NF * 32; idx += 256) {
            const int f = idx >> 5, yloc = idx & 31;
            const int dst = ((b * NF + f) * 64 + c) * 256 + ytile * 32 + yloc;
            g_Sr[dst] = __float2half_rn(fx_sm[FX_TSR + yloc * NF + f]);
            g_Si[dst] = __float2half_rn(fx_sm[FX_TSI + yloc * NF + f]);
        }
    } else {
        // -------- weight direct DFT --------
        const int ct = (int)blockIdx.x - 4096;    // 0..1983
        const int o  = ct & 63, ky = ct >> 6;
        float* sw   = fx_sm;                      // [64][31]
        float* ctab = fx_sm + 64 * 31;            // [512] cos
        float* stab = ctab + 512;                 // [512] sin
        for (int i = tid; i < 64 * 31; i += 256) {
            const int c = i / 31, kx = i - c * 31;
            sw[i] = w[((o * 64 + c) * 31 + ky) * 31 + kx];
        }
        for (int k = tid; k < 512; k += 256) {
            float s, cc;
            sincospif((float)k / 256.0f, &s, &cc);
            ctab[k] = cc; stab[k] = s;
        }
        __syncthreads();
        const int c  = tid & 63;
        const int fg = tid >> 6;                  // 0..3
        float wv[31];
#pragma unroll
        for (int kx = 0; kx < 31; kx++) wv[kx] = sw[c * 31 + kx];
        for (int f = fg; f < NF; f += 4) {
            float ar = 0.f, ai = 0.f;
#pragma unroll
            for (int kx = 0; kx < 31; kx++) {
                const int idx = (f * kx) & 511;
                ar = fmaf(wv[kx], ctab[idx], ar);
                ai = fmaf(wv[kx], stab[idx], ai);
            }
            // Wr = ar, Wi = -ai, Wd = Wr - Wi = ar + ai
            __half* base = (__half*)g_wA
                + ((size_t)(f * KS + ky) * COUT + o) * (WG_ROW * 2);
            base[c]       = __float2half_rn(ar);
            base[64 + c]  = __float2half_rn(-ai);
            base[128 + c] = __float2half_rn(ar + ai);
        }
    }
}

// ---------------------------------------------------------------------------
// Frequency-domain GEMM, Gauss 3-mult complex. Block = (b, ohalf, f).
//   t1 = Wr·Sr, t2 = Wi·Si, t3 = Wd·Ss  (Ss = Sr+Si)
//   Re = t1 + t2 ;  Im = t3 - t1 + t2
// sB: 96 pair-rows (SrP | SiP | SsP), col j = y'=j-15.
// sW: per (f,ky) o-half tile [32][ArP|AiP|AdP], cp.async double-buffered.
// 8 warps = y-slices of 32; per warp mt=2 (o), nt=4 -> 96 acc regs.
// ---------------------------------------------------------------------------
__device__ __forceinline__ void mma_f16(float* d, const unsigned* a,
                                        unsigned b0, unsigned b1) {
    asm volatile(
        "mma.sync.aligned.m16n8k16.row.col.f32.f16.f16.f32 "
        "{%0,%1,%2,%3}, {%4,%5,%6,%7}, {%8,%9}, {%0,%1,%2,%3};\n"
        : "+f"(d[0]), "+f"(d[1]), "+f"(d[2]), "+f"(d[3])
        : "r"(a[0]), "r"(a[1]), "r"(a[2]), "r"(a[3]), "r"(b0), "r"(b1));
}

__device__ __forceinline__ uint32_t s2u(const void* p) {
    uint32_t a;
    asm("{ .reg .u64 t; cvta.to.shared.u64 t, %1; cvt.u32.u64 %0, t; }" : "=r"(a) : "l"(p));
    return a;
}

extern __shared__ unsigned gx_sm[];

__global__ void __launch_bounds__(256, 1) freq_gemm() {
    const int tid = threadIdx.x, lane = tid & 31, warp = tid >> 5;
    const int g = lane >> 2, t4 = lane & 3;
    const int bx = blockIdx.x;                 // 0..15
    const int b = bx >> 1, oh = bx & 1;
    const int f = blockIdx.y;

    unsigned* sB = gx_sm;
    unsigned* sW = gx_sm + GX_WA;
    const uint32_t swu = s2u(sW);

    float t1[2][4][4], t2[2][4][4], t3[2][4][4];
#pragma unroll
    for (int mt = 0; mt < 2; mt++)
#pragma unroll
        for (int nt = 0; nt < 4; nt++)
#pragma unroll
            for (int r = 0; r < 4; r++) {
                t1[mt][nt][r] = 0.f; t2[mt][nt][r] = 0.f; t3[mt][nt][r] = 0.f;
            }

    // issue o-half A-tile(ky) -> slot ky&1 (32 rows x 96 u32 = 768 x 16B)
    auto issue_w = [&](int ky) {
        const float4* src = (const float4*)(g_wA
            + ((size_t)(f * KS + ky) * COUT + oh * 32) * WG_ROW);
        const uint32_t base = swu + (uint32_t)(ky & 1) * (WS_ELEMS * 4);
#pragma unroll
        for (int i = 0; i < 3; i++) {
            const int e = i * 256 + tid;        // 0..767
            const int row = e / 24, c16 = e - row * 24;
            asm volatile("cp.async.cg.shared.global [%0], [%1], 16;"
                         :: "r"(base + (uint32_t)(row * WS_STRIDE + c16 * 4) * 4u),
                            "l"(src + e) : "memory");
        }
        asm volatile("cp.async.commit_group;" ::: "memory");
    };

    issue_w(0);

    // fill sB: 96 pair-rows, 12 per warp; pack half2 per u32 store
    {
        const int rbase = warp * 12;
        const size_t sbase = ((size_t)(b * NF + f) * 64) << 8;
#pragma unroll 1
        for (int t = 0; t < 12; t++) {
            const int prow = rbase + t;          // 0..95
            const int grp = prow >> 5;           // 0:Sr 1:Si 2:Ss
            const int p = prow & 31;
            const __half* r0 = g_Sr + sbase + ((2 * p) << 8);
            const __half* r1 = r0 + 256;
            const __half* i0 = g_Si + sbase + ((2 * p) << 8);
            const __half* i1 = i0 + 256;
            unsigned* dst = sB + prow * SB_STRIDE;
            for (int j = lane; j < 286; j += 32) {
                unsigned u = 0;
                if (j >= 15 && j < 271) {
                    const int yy = j - 15;
                    __half2 v;
                    if (grp == 0)      v = __halves2half2(r0[yy], r1[yy]);
                    else if (grp == 1) v = __halves2half2(i0[yy], i1[yy]);
                    else               v = __hadd2(__halves2half2(r0[yy], r1[yy]),
                                                   __halves2half2(i0[yy], i1[yy]));
                    u = *(unsigned*)&v;
                }
                dst[j] = u;
            }
        }
    }

    for (int ky = 0; ky < KS; ky++) {
        asm volatile("cp.async.wait_group 0;" ::: "memory");
        __syncthreads();                    // A(ky)+sB visible; MMA(ky-1) done
        if (ky + 1 < KS) issue_w(ky + 1);

        const unsigned* wa = sW + (ky & 1) * WS_ELEMS;
#pragma unroll
        for (int cc = 0; cc < 4; cc++) {
            const int p0 = cc * 8 + t4;
            unsigned ar[2][4], ai[2][4], ad[2][4];
#pragma unroll
            for (int mt = 0; mt < 2; mt++) {
                const unsigned* pw = wa + (mt * 16 + g) * WS_STRIDE;
                ar[mt][0] = pw[p0];
                ar[mt][1] = pw[8 * WS_STRIDE + p0];
                ar[mt][2] = pw[p0 + 4];
                ar[mt][3] = pw[8 * WS_STRIDE + p0 + 4];
                ai[mt][0] = pw[32 + p0];
                ai[mt][1] = pw[8 * WS_STRIDE + 32 + p0];
                ai[mt][2] = pw[32 + p0 + 4];
                ai[mt][3] = pw[8 * WS_STRIDE + 32 + p0 + 4];
                ad[mt][0] = pw[64 + p0];
                ad[mt][1] = pw[8 * WS_STRIDE + 64 + p0];
                ad[mt][2] = pw[64 + p0 + 4];
                ad[mt][3] = pw[8 * WS_STRIDE + 64 + p0 + 4];
            }
            const int colb = warp * 32 + g + ky;
#pragma unroll
            for (int nt = 0; nt < 4; nt++) {
                const int col = colb + nt * 8;
                const unsigned br0 = sB[p0 * SB_STRIDE + col];
                const unsigned br1 = sB[(p0 + 4) * SB_STRIDE + col];
                const unsigned bi0 = sB[(32 + p0) * SB_STRIDE + col];
                const unsigned bi1 = sB[(36 + p0) * SB_STRIDE + col];
                const unsigned bs0 = sB[(64 + p0) * SB_STRIDE + col];
                const unsigned bs1 = sB[(68 + p0) * SB_STRIDE + col];
#pragma unroll
                for (int mt = 0; mt < 2; mt++) {
                    mma_f16(t1[mt][nt], ar[mt], br0, br1);
                    mma_f16(t2[mt][nt], ai[mt], bi0, bi1);
                    mma_f16(t3[mt][nt], ad[mt], bs0, bs1);
                }
            }
        }
    }

    // epilogue: Re = t1+t2, Im = t3-t1+t2 -> g_Or/g_Oi[f][b][o][y]
#pragma unroll
    for (int mt = 0; mt < 2; mt++) {
#pragma unroll
        for (int r = 0; r < 2; r++) {
            const int o = oh * 32 + mt * 16 + r * 8 + g;
            const int base = ((f * NBATCH + b) * COUT + o) << 8;
#pragma unroll
            for (int nt = 0; nt < 4; nt++) {
                const int y = warp * 32 + nt * 8 + t4 * 2;
                float2 vr, vi;
                const float a0 = t1[mt][nt][r * 2 + 0], a1 = t1[mt][nt][r * 2 + 1];
                const float b0 = t2[mt][nt][r * 2 + 0], b1 = t2[mt][nt][r * 2 + 1];
                const float c0 = t3[mt][nt][r * 2 + 0], c1 = t3[mt][nt][r * 2 + 1];
                vr.x = a0 + b0;        vr.y = a1 + b1;
                vi.x = c0 - a0 + b0;   vi.y = c1 - a1 + b1;
                *(float2*)(g_Or + base + y) = vr;
                *(float2*)(g_Oi + base + y) = vi;
            }
        }
    }
}

// ---------------------------------------------------------------------------
// Inverse rfft + shift + bias. CTA = (b, o, ytile of 32).
// ---------------------------------------------------------------------------
__global__ void __launch_bounds__(256) inv_fft(const float* __restrict__ bias,
                                               float* __restrict__ out) {
    const int tid = threadIdx.x, lane = tid & 31, warp = tid >> 5;
    const int ct = blockIdx.x;
    const int ytile = ct & 7, o = (ct >> 3) & 63, b = ct >> 9;
    const int y0 = ytile * 32;
    load_tw(fx_sm, tid);
    __syncthreads();
    for (int idx = tid; idx < NF * 32; idx += 256) {
        const int f = idx >> 5, yloc = idx & 31;
        const int src = ((f * NBATCH + b) * COUT + o) * 256 + y0 + yloc;
        fx_sm[FX_TSR + yloc * NF + f] = g_Or[src];
        fx_sm[FX_TSI + yloc * NF + f] = g_Oi[src];
    }
    __syncthreads();
    const float bv = __ldg(bias + o);
    for (int batch = 0; batch < 4; batch++) {
        const int yloc = batch * 8 + warp;
        const int y = y0 + yloc;
        float* fr = fx_sm + FX_ROW + warp * 512;
        float* fi = fr + 256;
        const float* tsr = fx_sm + FX_TSR + yloc * NF;
        const float* tsi = fx_sm + FX_TSI + yloc * NF;
        for (int k = lane; k < 256; k += 32) {
            const float Skr = tsr[k],       Ski = tsi[k];
            const float Smr = tsr[256 - k], Smi = tsi[256 - k];
            const float Fer = 0.5f * (Skr + Smr);
            const float Fei = 0.5f * (Ski - Smi);
            const float Dr = Skr - Smr;
            const float Di = Ski + Smi;
            const float wr = fx_sm[FX_T512R + k];
            const float wi = -fx_sm[FX_T512I + k];
            const float For = 0.5f * (wr * Dr - wi * Di);
            const float Foi = 0.5f * (wr * Di + wi * Dr);
            const float Zr = Fer - Foi;
            const float Zi = Fei + For;
            const int r = rev4(k);
            fr[r] = Zr; fi[r] = -Zi;               // conj(Z)
        }
        __syncwarp();
        fft256_r4(fr, fi, fx_sm + FX_T256R, fx_sm + FX_T256I, lane);
        float* orow = out + (((b * COUT + o) * 256 + y) << 8);
        const float inv = 1.0f / 256.0f;
        for (int x = lane; x < 256; x += 32) {
            const int n2 = (x + 497) & 511;        // (x - 15) mod 512
            const int h = n2 >> 1;
            const float v = (n2 & 1) ? (-fi[h]) : fr[h];
            orow[x] = v * inv + bv;
        }
        __syncwarp();
    }
}

// ---------------------------------------------------------------------------
extern "C" void kernel_launch(void* const* d_in, const int* in_sizes, int n_in,
                              void* d_out, int out_size) {
    const float* sig  = (const float*)d_in[0];
    const float* w    = (const float*)d_in[1];
    const float* bias = (const float*)d_in[2];
    float* out        = (float*)d_out;

    const size_t fx_bytes = (size_t)FX_TOTAL * sizeof(float);     // 86,280
    const size_t gx_bytes = (size_t)GX_TOTAL * sizeof(unsigned);  // 139,264
    cudaFuncSetAttribute(fwd_fft,  cudaFuncAttributeMaxDynamicSharedMemorySize, (int)fx_bytes);
    cudaFuncSetAttribute(inv_fft,  cudaFuncAttributeMaxDynamicSharedMemorySize, (int)fx_bytes);
    cudaFuncSetAttribute(freq_gemm, cudaFuncAttributeMaxDynamicSharedMemorySize, (int)gx_bytes);

    tw_init<<<1, 512>>>();
    fwd_fft<<<4096 + KS * COUT, 256, fx_bytes>>>(sig, w);       // 4096 sig + 1984 w
    freq_gemm<<<dim3(2 * NBATCH, NF), 256, gx_bytes>>>();       // (b, ohalf) x f
    inv_fft<<<NBATCH * COUT * 8, 256, fx_bytes>>>(bias, out);   // 4096 CTAs
}